// round 15
// baseline (speedup 1.0000x reference)
#include <cuda_runtime.h>

// ProductVectorQuantizer: B=64,T=2048,D=512, C=4,K=128,d=128
// out (float32) = [quantized (N*512), encoding_indices (N), loss (N)]

#define CB    4
#define KC    128
#define ROWS  64
#define NTHR  256
#define JC4   32      // float4 chunks per 128-float segment
#define EKP   129     // k-stride (in float4) of transposed E tile: E_s[jc][k]
#define XPAD  33      // float4 stride per x row
#define BSTP  9       // row stride (u64) of per-warp bests table

__device__ float e2g[CB * KC];   // ||E_ck||^2, filled by prologue kernel

__global__ void e2_kernel(const float* __restrict__ gemb) {
    int c = blockIdx.x, k = threadIdx.x;           // 4 blocks x 128 threads
    const float4* row = (const float4*)(gemb + ((size_t)c * KC + k) * 128);
    float s = 0.0f;
    #pragma unroll
    for (int jc = 0; jc < JC4; ++jc) {
        float4 e = row[jc];
        s += e.x * e.x + e.y * e.y + e.z * e.z + e.w * e.w;
    }
    e2g[c * KC + k] = s;
}

__device__ __forceinline__ void ffma2(unsigned long long &a,
                                      unsigned long long x,
                                      unsigned long long e) {
    asm("fma.rn.f32x2 %0, %1, %2, %0;" : "+l"(a) : "l"(x), "l"(e));
}

extern __shared__ float4 smem4[];

__global__ __launch_bounds__(NTHR, 2)
void pvq_kernel(const float* __restrict__ gin, const float* __restrict__ gemb,
                float* __restrict__ gout, int Nrows)
{
    float4* E_s = smem4;                             // [32][129] f4 : E_s[jc*EKP + k]
    float4* x_s = E_s + JC4 * EKP;                   // [64][33]  f4 : x_s[row*XPAD + jc]
    float*  e2_s = (float*)(x_s + ROWS * XPAD);      // [128]
    unsigned long long* bests = (unsigned long long*)(e2_s + KC);  // [64][BSTP]
    float* loss_s = (float*)(bests + ROWS * BSTP);   // [64]
    int*   pack_s = (int*)(loss_s + ROWS);           // [64]
    int*   idx_s  = pack_s + ROWS;                   // [64]

    const int t    = threadIdx.x;
    const int w    = t >> 5;
    const int lane = t & 31;
    const int cq   = lane & 3;      // code sub-lane in quad
    const int rg   = lane >> 2;     // row group 0..7 (thread rows: rg + 8*rr)
    const int cg   = (w << 2) | cq; // code group 0..31 (thread codes: 32*i + cg)
    const int n0   = blockIdx.x * ROWS;

    if (t < ROWS) { loss_s[t] = 0.0f; pack_s[t] = 0; }

    for (int c = 0; c < CB; ++c) {
        __syncthreads();   // previous phase fully consumed before overwrite

        // ---- stage codebook c (transposed): gmem [k][jc] -> E_s[jc][k] ----
        const float4* gE = (const float4*)(gemb + (size_t)c * KC * 128);
        #pragma unroll
        for (int it = 0; it < (KC * JC4) / NTHR; ++it) {
            int idx = it * NTHR + t;
            int k = idx >> 5, jc = idx & 31;
            E_s[jc * EKP + k] = gE[idx];
        }
        // ---- stage x tile: 64 rows, segment c ----
        const float4* gx = (const float4*)gin;
        #pragma unroll
        for (int it = 0; it < (ROWS * JC4) / NTHR; ++it) {
            int idx = it * NTHR + t;
            int row = idx >> 5, jc = idx & 31;
            x_s[row * XPAD + jc] = gx[(size_t)(n0 + row) * 128 + c * 32 + jc];
        }
        if (t < KC) e2_s[t] = e2g[c * KC + t];     // precomputed norms
        __syncthreads();

        // ---- dots: thread computes 8 rows x 4 codes, f32x2-packed over j ----
        unsigned long long acc[8][4];
        #pragma unroll
        for (int rr = 0; rr < 8; ++rr)
            #pragma unroll
            for (int i = 0; i < 4; ++i) acc[rr][i] = 0ULL;

        const ulonglong2* Ev = (const ulonglong2*)E_s;
        const ulonglong2* Xv = (const ulonglong2*)x_s;

        #pragma unroll 4
        for (int jc = 0; jc < JC4; ++jc) {
            unsigned long long xa[8][2];
            #pragma unroll
            for (int rr = 0; rr < 8; ++rr) {       // 8 distinct addrs, banks 4*rg: 1 phase
                ulonglong2 v = Xv[(rg + 8 * rr) * XPAD + jc];
                xa[rr][0] = v.x; xa[rr][1] = v.y;
            }
            #pragma unroll
            for (int i = 0; i < 4; ++i) {          // 4 contiguous addrs: 1 phase
                ulonglong2 ev = Ev[jc * EKP + (32 * i + cg)];
                #pragma unroll
                for (int rr = 0; rr < 8; ++rr) {
                    ffma2(acc[rr][i], xa[rr][0], ev.x);
                    ffma2(acc[rr][i], xa[rr][1], ev.y);
                }
            }
        }

        // ---- argmin: per-thread over 4 codes, then quad (4 lanes), then warps ----
        #pragma unroll
        for (int rr = 0; rr < 8; ++rr) {
            float best = 3.0e38f; int bk = KC;
            #pragma unroll
            for (int i = 0; i < 4; ++i) {
                int k = 32 * i + cg;
                float lo, hi;
                asm("mov.b64 {%0,%1}, %2;" : "=f"(lo), "=f"(hi) : "l"(acc[rr][i]));
                float score = e2_s[k] - 2.0f * (lo + hi);
                if (score < best || (score == best && k < bk)) { best = score; bk = k; }
            }
            #pragma unroll
            for (int off = 1; off <= 2; off <<= 1) {   // reduce over code-quad
                float v2 = __shfl_xor_sync(0xffffffffu, best, off);
                int   k2 = __shfl_xor_sync(0xffffffffu, bk,   off);
                if (v2 < best || (v2 == best && k2 < bk)) { best = v2; bk = k2; }
            }
            if (cq == 0) {                             // lane 4*rg publishes row's best
                unsigned u = __float_as_uint(best);
                u = (u & 0x80000000u) ? ~u : (u | 0x80000000u);   // order-preserving
                bests[(rg + 8 * rr) * BSTP + w] =
                    ((unsigned long long)u << 32) | (unsigned)bk;
            }
        }
        __syncthreads();

        // ---- combine 8 warps per row; min key = (min score, tie -> min k) ----
        if (t < ROWS) {
            unsigned long long m = bests[t * BSTP + 0];
            #pragma unroll
            for (int j = 1; j < 8; ++j) {
                unsigned long long v = bests[t * BSTP + j];
                if (v < m) m = v;
            }
            int k = (int)(m & 0xffffffffu);
            idx_s[t] = k;
            pack_s[t] += k << (21 - 7 * c);            // K^(3-c) as shift (K=128)
        }
        __syncthreads();

        // ---- gather quantized, write out, exact loss ||q-x||^2 accumulation ----
        #pragma unroll
        for (int it = 0; it < 8; ++it) {
            int row = it * 8 + w;                      // one warp per row
            int k   = idx_s[row];
            float4 e  = E_s[lane * EKP + k];
            float4 xv = x_s[row * XPAD + lane];
            ((float4*)gout)[(size_t)(n0 + row) * 128 + c * 32 + lane] = e;
            float dx = e.x - xv.x, dy = e.y - xv.y,
                  dz = e.z - xv.z, dw = e.w - xv.w;
            float s = dx * dx + dy * dy + dz * dz + dw * dw;
            #pragma unroll
            for (int off = 16; off > 0; off >>= 1)
                s += __shfl_xor_sync(0xffffffffu, s, off);
            if (lane == 0) loss_s[row] += s;
        }
    }

    __syncthreads();
    if (t < ROWS) {
        size_t n = (size_t)n0 + t;
        float* idx_out  = gout + (size_t)Nrows * 512;
        float* loss_out = idx_out + Nrows;
        idx_out[n]  = (float)pack_s[t];
        loss_out[n] = 1.25f * loss_s[t];   // q_latent + COMMITMENT_COST*e_latent
    }
}

extern "C" void kernel_launch(void* const* d_in, const int* in_sizes, int n_in,
                              void* d_out, int out_size)
{
    const float* gin  = (const float*)d_in[0];   // inputs (B,T,D) f32
    const float* gemb = (const float*)d_in[1];   // embeddings (C,K,d) f32
    int Nrows = in_sizes[0] / 512;               // 131072

    int smem = (JC4 * EKP + ROWS * XPAD) * 16    // E_s + x_s
             + KC * 4                            // e2_s
             + ROWS * BSTP * 8                   // bests
             + ROWS * 4 * 3;                     // loss + pack + idx
    cudaFuncSetAttribute(pvq_kernel, cudaFuncAttributeMaxDynamicSharedMemorySize, smem);

    e2_kernel<<<CB, KC>>>(gemb);
    pvq_kernel<<<Nrows / ROWS, NTHR, smem>>>(gin, gemb, (float*)d_out, Nrows);
}